// round 9
// baseline (speedup 1.0000x reference)
#include <cuda_runtime.h>
#include <cstdint>
#include <cstddef>

constexpr int B_  = 64;
constexpr int L_  = 1024;
constexpr int DK_ = 64;
constexpr int P_  = 2047;              // 2*L-1
constexpr float INV_TEMPER = 0.125f;   // 1/sqrt(64)

constexpr int TILE_L    = 16;
constexpr int NTHREADS  = 512;
constexpr int SL_STRIDE = 1028;        // 1024 + pad
constexpr int CK_STRIDE = 12;          // 8 floats + 4 pad (48B; lane*12 mod 32 conflict-free)
constexpr int CK_ROWS   = 1024;        // main GEMM only ever reads rows < 1024
constexpr int BUF_FLOATS = CK_ROWS * CK_STRIDE;   // 12288 floats per buffer
constexpr int NHC       = 8;           // 8 half-chunks of 8 dc-floats = DK 64

constexpr int SMEM_FLOATS = TILE_L*64*2            // sQ, sQr (direct)
                          + TILE_L*64*2            // sQp, sQrp (row-pair packed)
                          + TILE_L*SL_STRIDE       // sL (bias -> logits -> probs)
                          + 2*BUF_FLOATS           // sCK double buffer
                          + 16;                    // sInv
constexpr int SMEM_BYTES = SMEM_FLOATS * 4;        // 180,544 B

// 1 => mask elements 4 bytes wide (int32/float32, nonzero == masked); 0 => 1-byte bool
__device__ int g_mask_w4;

__global__ void detect_mask_kernel(const unsigned char* __restrict__ m)
{
    __shared__ int s_w1, s_f32;
    if (threadIdx.x == 0) { s_w1 = 0; s_f32 = 0; }
    __syncthreads();
    for (int i = threadIdx.x; i < 65536; i += blockDim.x) {
        const unsigned char bb = m[i];
        if (bb > 1) s_f32 = 1;
        else if (bb == 1 && (i & 3) != 0) s_w1 = 1;
    }
    __syncthreads();
    if (threadIdx.x == 0) g_mask_w4 = (s_f32 || !s_w1) ? 1 : 0;
}

// ---------------- packed f32x2 helpers (sm_103a FFMA2 path) ----------------
__device__ __forceinline__ unsigned long long pack2(float lo, float hi) {
    unsigned long long r;
    asm("mov.b64 %0, {%1, %2};" : "=l"(r) : "f"(lo), "f"(hi));
    return r;
}
__device__ __forceinline__ unsigned long long splat2(float v) {
    unsigned long long r;
    asm("mov.b64 %0, {%1, %1};" : "=l"(r) : "f"(v));
    return r;
}
__device__ __forceinline__ unsigned long long fma2(unsigned long long a,
                                                   unsigned long long b,
                                                   unsigned long long c) {
    unsigned long long d;
    asm("fma.rn.f32x2 %0, %1, %2, %3;" : "=l"(d) : "l"(a), "l"(b), "l"(c));
    return d;
}
__device__ __forceinline__ float2 unpack2(unsigned long long v) {
    float lo, hi;
    asm("mov.b64 {%0, %1}, %2;" : "=f"(lo), "=f"(hi) : "l"(v));
    return make_float2(lo, hi);
}

// ---------------- cp.async helpers ----------------
__device__ __forceinline__ void cp_async16(uint32_t dst_smem, const void* src) {
    asm volatile("cp.async.cg.shared.global [%0], [%1], 16;"
                 :: "r"(dst_smem), "l"(src) : "memory");
}
__device__ __forceinline__ void cp_commit() {
    asm volatile("cp.async.commit_group;" ::: "memory");
}
__device__ __forceinline__ void cp_wait1() {
    asm volatile("cp.async.wait_group 1;" ::: "memory");
}
__device__ __forceinline__ void cp_wait0() {
    asm volatile("cp.async.wait_group 0;" ::: "memory");
}

__device__ __forceinline__ float dot4(float4 a, float4 b) {
    return a.x*b.x + a.y*b.y + a.z*b.z + a.w*b.w;
}

__device__ __forceinline__ uint32_t smem_u32(const void* p) {
    return (uint32_t)__cvta_generic_to_shared(p);
}

__global__ void __launch_bounds__(NTHREADS, 1)
attn_fused_kernel(const float* __restrict__ gq, const float* __restrict__ gk,
                  const float* __restrict__ gv, const float* __restrict__ gpos,
                  const void* __restrict__ gmask,
                  float* __restrict__ gout, float* __restrict__ gattn)
{
    extern __shared__ float smem[];
    float* sQ   = smem;                          // [16][64]  direct
    float* sQr  = sQ   + TILE_L*64;              // [16][64]  direct
    float* sQp  = sQr  + TILE_L*64;              // [64][8] f32x2 row-pairs of Q
    float* sQrp = sQp  + TILE_L*64;              // [64][8] f32x2 row-pairs of Qr
    float* sL   = sQrp + TILE_L*64;              // [16][1028]
    float* sCK  = sL   + TILE_L*SL_STRIDE;       // 2 x [1024][12] staging
    float* sInv = sCK  + 2*BUF_FLOATS;           // [16]

    const int b   = blockIdx.y;
    const int l0  = blockIdx.x * TILE_L;
    const int tid = threadIdx.x;
    const int mask_w4 = g_mask_w4;
    const float NEG_INF = __int_as_float(0xff800000);

    const uint32_t ck_u32 = smem_u32(sCK);

    // ---------- Phase 0: load Q / reversed-Q rows, then build packed copies ----------
    {
        const int h = tid & 255;
        const int r = h >> 4, q4 = (h & 15) * 4;
        if (tid < 256)
            *(float4*)(sQ + r*64 + q4) =
                *(const float4*)(gq + ((size_t)b*L_ + (l0 + r))*DK_ + q4);
        else
            *(float4*)(sQr + r*64 + q4) =
                *(const float4*)(gq + ((size_t)b*L_ + (L_ - 1 - (l0 + r)))*DK_ + q4);
    }
    __syncthreads();
    {
        // packed layout: sQp[(e*8 + p)*2 + (r&1)] = sQ[r][e], p = r>>1
        #pragma unroll
        for (int t = 0; t < 2; ++t) {
            const int j = tid*2 + t;
            const int r = j >> 6, e = j & 63;
            const int di = (e*8 + (r >> 1))*2 + (r & 1);
            sQp[di]  = sQ[r*64 + e];
            sQrp[di] = sQr[r*64 + e];
        }
    }

    const int r0 = tid, r1 = tid + 512;

    // staging map: j = tid + i*512, i<4 -> row = j>>1, h = j&1
    // src bytes: row*256 + c*32 + h*16 ; dst bytes: buf + row*48 + h*16
    const int st_row = tid >> 1;          // rows for i=0 ; +256 per i
    const int st_h   = tid & 1;

    // acc2[p][col]: rows (2p, 2p+1) packed, col 0 -> m=r0, col 1 -> m=r1
    unsigned long long acc2[8][2];

    __syncthreads();   // packed arrays ready

    // ======== Phases 1 & 2 share this GEMM skeleton (A = packed Qr or Q) ========
    #pragma unroll 1
    for (int phase = 0; phase < 2; ++phase) {
        const float* ap  = phase == 0 ? sQrp : sQp;
        const float* src = phase == 0 ? gpos + ((size_t)b*P_ + l0)*DK_
                                      : gk   + ((size_t)b*L_)*DK_;

        #pragma unroll
        for (int p = 0; p < 8; ++p) { acc2[p][0] = 0ull; acc2[p][1] = 0ull; }

        // ---- stage half-chunks 0 and 1 into buffers 0 and 1 ----
        #pragma unroll
        for (int i = 0; i < 4; ++i) {
            const int row = st_row + i*256;
            cp_async16(ck_u32 + (uint32_t)(row*48 + st_h*16),
                       src + (size_t)row*DK_ + st_h*4);
        }
        cp_commit();
        #pragma unroll
        for (int i = 0; i < 4; ++i) {
            const int row = st_row + i*256;
            cp_async16(ck_u32 + (uint32_t)(BUF_FLOATS*4 + row*48 + st_h*16),
                       src + (size_t)row*DK_ + 8 + st_h*4);
        }
        cp_commit();

        #pragma unroll 1
        for (int c = 0; c < NHC; ++c) {
            if (c < NHC-1) cp_wait1(); else cp_wait0();
            __syncthreads();                 // chunk c visible to all

            const float* ckbuf = sCK + (c & 1) * BUF_FLOATS;
            #pragma unroll
            for (int s4 = 0; s4 < 2; ++s4) {
                const float4 kv0 = *(const float4*)(ckbuf + r0*CK_STRIDE + s4*4);
                const float4 kv1 = *(const float4*)(ckbuf + r1*CK_STRIDE + s4*4);
                const int dcb = (c*8 + s4*4) * 16;  // float index into packed A
                #pragma unroll
                for (int e = 0; e < 4; ++e) {
                    const float ke0 = e==0?kv0.x : e==1?kv0.y : e==2?kv0.z : kv0.w;
                    const float ke1 = e==0?kv1.x : e==1?kv1.y : e==2?kv1.z : kv1.w;
                    const unsigned long long k0 = splat2(ke0);
                    const unsigned long long k1 = splat2(ke1);
                    const ulonglong2* a2 = (const ulonglong2*)(ap + dcb + e*16);
                    const ulonglong2 a01 = a2[0], a23 = a2[1], a45 = a2[2], a67 = a2[3];
                    acc2[0][0] = fma2(a01.x, k0, acc2[0][0]);
                    acc2[0][1] = fma2(a01.x, k1, acc2[0][1]);
                    acc2[1][0] = fma2(a01.y, k0, acc2[1][0]);
                    acc2[1][1] = fma2(a01.y, k1, acc2[1][1]);
                    acc2[2][0] = fma2(a23.x, k0, acc2[2][0]);
                    acc2[2][1] = fma2(a23.x, k1, acc2[2][1]);
                    acc2[3][0] = fma2(a23.y, k0, acc2[3][0]);
                    acc2[3][1] = fma2(a23.y, k1, acc2[3][1]);
                    acc2[4][0] = fma2(a45.x, k0, acc2[4][0]);
                    acc2[4][1] = fma2(a45.x, k1, acc2[4][1]);
                    acc2[5][0] = fma2(a45.y, k0, acc2[5][0]);
                    acc2[5][1] = fma2(a45.y, k1, acc2[5][1]);
                    acc2[6][0] = fma2(a67.x, k0, acc2[6][0]);
                    acc2[6][1] = fma2(a67.x, k1, acc2[6][1]);
                    acc2[7][0] = fma2(a67.y, k0, acc2[7][0]);
                    acc2[7][1] = fma2(a67.y, k1, acc2[7][1]);
                }
            }
            __syncthreads();                 // all done with buffer (c&1)

            if (c + 2 < NHC) {               // stage chunk c+2 into buffer (c&1)
                const uint32_t dbase = ck_u32 + (uint32_t)((c & 1) * BUF_FLOATS * 4);
                #pragma unroll
                for (int i = 0; i < 4; ++i) {
                    const int row = st_row + i*256;
                    cp_async16(dbase + (uint32_t)(row*48 + st_h*16),
                               src + (size_t)row*DK_ + (c+2)*8 + st_h*4);
                }
                cp_commit();
            }
        }

        if (phase == 0) {
            // scatter bias: sL[i][s - i] = G[i][s]  (each (i,m) written exactly once)
            #pragma unroll
            for (int p = 0; p < 8; ++p) {
                const float2 g0 = unpack2(acc2[p][0]);   // rows 2p, 2p+1 at s=r0
                const float2 g1 = unpack2(acc2[p][1]);   // rows 2p, 2p+1 at s=r1
                const int i0 = 2*p, i1 = 2*p + 1;
                int m;
                m = r0 - i0; if (m >= 0)   sL[i0*SL_STRIDE + m] = g0.x;
                m = r0 - i1; if (m >= 0)   sL[i1*SL_STRIDE + m] = g0.y;
                m = r1 - i0; if (m < 1024) sL[i0*SL_STRIDE + m] = g1.x;
                m = r1 - i1; if (m < 1024) sL[i1*SL_STRIDE + m] = g1.y;
            }
            __syncthreads();

            // tail cols s = 1024..1038
            if (tid < 240) {   // stage 15 rows x 64 floats (buffers are free now)
                const int row = tid >> 4, q4 = (tid & 15)*4;
                *(float4*)(sCK + row*68 + q4) =
                    *(const float4*)(src + (size_t)(1024 + row)*DK_ + q4);
            }
            __syncthreads();
            if (tid < 15) {
                const int s = 1024 + tid;
                float accT[16];
                #pragma unroll
                for (int i = 0; i < 16; ++i) accT[i] = 0.f;
                #pragma unroll
                for (int q = 0; q < 16; ++q) {
                    const float4 kv = *(const float4*)(sCK + tid*68 + q*4);
                    #pragma unroll
                    for (int i = 0; i < 16; ++i) {
                        const float4 a = *(const float4*)(sQr + i*64 + q*4);
                        accT[i] += dot4(a, kv);
                    }
                }
                #pragma unroll
                for (int i = 0; i < 16; ++i) {
                    const int m = s - i;
                    if (m < 1024) sL[i*SL_STRIDE + m] = accT[i];
                }
            }
            __syncthreads();
        } else {
            // combine with bias (already in sL), apply mask, write logits
            float accv[16][2];
            #pragma unroll
            for (int p = 0; p < 8; ++p) {
                const float2 g0 = unpack2(acc2[p][0]);
                const float2 g1 = unpack2(acc2[p][1]);
                accv[2*p  ][0] = g0.x; accv[2*p+1][0] = g0.y;
                accv[2*p  ][1] = g1.x; accv[2*p+1][1] = g1.y;
            }
            if (mask_w4) {
                const int* mbase = (const int*)gmask + ((size_t)b*L_ + l0)*L_;
                #pragma unroll
                for (int i = 0; i < 16; ++i) {
                    const int mk0 = mbase[(size_t)i*L_ + r0];
                    const int mk1 = mbase[(size_t)i*L_ + r1];
                    float* p0 = sL + i*SL_STRIDE + r0;
                    float* p1 = sL + i*SL_STRIDE + r1;
                    *p0 = mk0 ? NEG_INF : (accv[i][0] + *p0) * INV_TEMPER;
                    *p1 = mk1 ? NEG_INF : (accv[i][1] + *p1) * INV_TEMPER;
                }
            } else {
                const unsigned char* mbase = (const unsigned char*)gmask + ((size_t)b*L_ + l0)*L_;
                #pragma unroll
                for (int i = 0; i < 16; ++i) {
                    const unsigned char mk0 = mbase[(size_t)i*L_ + r0];
                    const unsigned char mk1 = mbase[(size_t)i*L_ + r1];
                    float* p0 = sL + i*SL_STRIDE + r0;
                    float* p1 = sL + i*SL_STRIDE + r1;
                    *p0 = mk0 ? NEG_INF : (accv[i][0] + *p0) * INV_TEMPER;
                    *p1 = mk1 ? NEG_INF : (accv[i][1] + *p1) * INV_TEMPER;
                }
            }
            __syncthreads();
        }
    }

    // ================== Phase 3: softmax (one warp per row) + attn writeback ==========
    {
        const int row  = tid >> 5;     // 16 warps -> 16 rows
        const int lane = tid & 31;
        float* rowp = sL + row*SL_STRIDE;

        float mx = NEG_INF;
        #pragma unroll
        for (int j = 0; j < 8; ++j) {
            const float4 vv = *(const float4*)(rowp + j*128 + lane*4);
            mx = fmaxf(mx, fmaxf(fmaxf(vv.x, vv.y), fmaxf(vv.z, vv.w)));
        }
        #pragma unroll
        for (int o = 16; o; o >>= 1) mx = fmaxf(mx, __shfl_xor_sync(0xffffffffu, mx, o));

        float sum = 0.f;
        #pragma unroll
        for (int j = 0; j < 8; ++j) {
            float4 vv = *(float4*)(rowp + j*128 + lane*4);
            vv.x = __expf(vv.x - mx); vv.y = __expf(vv.y - mx);
            vv.z = __expf(vv.z - mx); vv.w = __expf(vv.w - mx);
            sum += (vv.x + vv.y) + (vv.z + vv.w);
            *(float4*)(rowp + j*128 + lane*4) = vv;   // unnormalized exp kept in sL
        }
        #pragma unroll
        for (int o = 16; o; o >>= 1) sum += __shfl_xor_sync(0xffffffffu, sum, o);
        const float inv = 1.f / sum;
        if (lane == 0) sInv[row] = inv;

        float* arow = gattn + ((size_t)b*L_ + (l0 + row))*L_;
        #pragma unroll
        for (int j = 0; j < 8; ++j) {
            float4 vv = *(const float4*)(rowp + j*128 + lane*4);
            vv.x *= inv; vv.y *= inv; vv.z *= inv; vv.w *= inv;
            *(float4*)(arow + j*128 + lane*4) = vv;
        }
    }
    __syncthreads();

    // ================== Phase 4: output = (exp-probs @ V) * inv =====================
    {
        const int cg = tid & 15;          // d-cols 4cg..4cg+3
        const int rg = (tid >> 4) & 3;    // rows 4rg..4rg+3
        const int ms = tid >> 6;          // 8 m-splits of 128

        // accp2[i][h]: row rg*4+i, h=0 -> d-cols (4cg,4cg+1), h=1 -> (4cg+2,4cg+3)
        unsigned long long accp2[4][2];
        #pragma unroll
        for (int i = 0; i < 4; ++i) { accp2[i][0] = 0ull; accp2[i][1] = 0ull; }

        const float* vbase = gv + ((size_t)b*L_ + ms*128)*DK_ + cg*4;
        const float* pbase = sL + (rg*4)*SL_STRIDE + ms*128;

        #pragma unroll 4
        for (int mm = 0; mm < 128; mm += 2) {
            const float4 v0 = *(const float4*)(vbase + (size_t)mm*DK_);
            const float4 v1 = *(const float4*)(vbase + (size_t)(mm+1)*DK_);
            const unsigned long long v0a = pack2(v0.x, v0.y), v0b = pack2(v0.z, v0.w);
            const unsigned long long v1a = pack2(v1.x, v1.y), v1b = pack2(v1.z, v1.w);
            #pragma unroll
            for (int i = 0; i < 4; ++i) {
                const float2 p = *(const float2*)(pbase + i*SL_STRIDE + mm);
                const unsigned long long pp0 = splat2(p.x);
                const unsigned long long pp1 = splat2(p.y);
                accp2[i][0] = fma2(pp0, v0a, accp2[i][0]);
                accp2[i][0] = fma2(pp1, v1a, accp2[i][0]);
                accp2[i][1] = fma2(pp0, v0b, accp2[i][1]);
                accp2[i][1] = fma2(pp1, v1b, accp2[i][1]);
            }
        }
        // partials: sCK[(ms*16 + row)*16 + cg] as float4
        #pragma unroll
        for (int i = 0; i < 4; ++i) {
            const float2 lo = unpack2(accp2[i][0]);
            const float2 hi = unpack2(accp2[i][1]);
            *(float4*)(sCK + (size_t)((ms*16 + rg*4 + i)*16 + cg)*4) =
                make_float4(lo.x, lo.y, hi.x, hi.y);
        }
    }
    __syncthreads();

    if (tid < 256) {
        const int row = tid >> 4, cg = tid & 15;
        float4 s = make_float4(0.f,0.f,0.f,0.f);
        #pragma unroll
        for (int ms = 0; ms < 8; ++ms) {
            const float4 p = *(const float4*)(sCK + (size_t)((ms*16 + row)*16 + cg)*4);
            s.x += p.x; s.y += p.y; s.z += p.z; s.w += p.w;
        }
        const float inv = sInv[row];
        s.x *= inv; s.y *= inv; s.z *= inv; s.w *= inv;
        *(float4*)(gout + ((size_t)b*L_ + (l0 + row))*DK_ + cg*4) = s;
    }
}

extern "C" void kernel_launch(void* const* d_in, const int* in_sizes, int n_in,
                              void* d_out, int out_size)
{
    // Identify inputs by element count; q,k,v in encounter order.
    const float* q   = nullptr;
    const float* k   = nullptr;
    const float* v   = nullptr;
    const float* pos = nullptr;
    const void*  mask = nullptr;
    int qkv_seen = 0;
    for (int i = 0; i < n_in; ++i) {
        const long long sz = in_sizes[i];
        if (sz == (long long)B_ * P_ * DK_) {
            pos = (const float*)d_in[i];
        } else if (sz == (long long)B_ * L_ * L_) {
            mask = d_in[i];
        } else if (sz == (long long)B_ * L_ * DK_) {
            if      (qkv_seen == 0) q = (const float*)d_in[i];
            else if (qkv_seen == 1) k = (const float*)d_in[i];
            else                    v = (const float*)d_in[i];
            ++qkv_seen;
        }
    }

    float* out  = (float*)d_out;                       // (B, L, DK) first
    float* attn = out + (size_t)B_ * L_ * DK_;         // (B, L, L) second

    cudaFuncSetAttribute(attn_fused_kernel,
                         cudaFuncAttributeMaxDynamicSharedMemorySize, SMEM_BYTES);

    detect_mask_kernel<<<1, 256>>>((const unsigned char*)mask);

    dim3 grid(L_ / TILE_L, B_);
    attn_fused_kernel<<<grid, NTHREADS, SMEM_BYTES>>>(q, k, v, pos, mask, out, attn);
}